// round 1
// baseline (speedup 1.0000x reference)
#include <cuda_runtime.h>
#include <math.h>

#define D_ 256
#define B_ 128
#define S_ 1024
#define NROWS (B_*S_)
#define NCH 8
#define NBLK 592
#define CLAMPF 1e-7f

// ---- scratch (static device globals; no allocations) ----
__device__ float g_part1[B_*NCH*D_];   // per (batch, seq-chunk) feature sums
__device__ float g_cb[B_*D_];          // per-batch seq centroids (normalized)
__device__ float g_mean[D_];           // final Frechet-style centroid
__device__ float g_part2[NBLK*2*D_];   // per-block [sum(256) | sumsq(256)] partials
__device__ float g_scale[D_];          // gamma / sqrt(var + eps)

__device__ __forceinline__ float wsum(float v){
#pragma unroll
  for(int o=16;o>0;o>>=1) v += __shfl_xor_sync(0xffffffffu, v, o);
  return v;
}

// ---------------- Pass 1: seq-chunk partial sums ----------------
__global__ void __launch_bounds__(256) kA(const float* __restrict__ x){
  int b = blockIdx.x / NCH, c = blockIdx.x % NCH;
  int t = threadIdx.x;
  const float* p = x + ((size_t)b*S_ + (size_t)c*(S_/NCH))*D_ + t;
  float acc = 0.f;
#pragma unroll 8
  for(int s=0;s<S_/NCH;s++) acc += p[(size_t)s*D_];
  g_part1[(size_t)blockIdx.x*D_ + t] = acc;
}

// centroid over seq per batch (normalization is scale invariant: skip /S)
__global__ void __launch_bounds__(256) kA2(){
  __shared__ float red[256];
  int b = blockIdx.x, t = threadIdx.x;
  float avg = 0.f;
#pragma unroll
  for(int c=0;c<NCH;c++) avg += g_part1[(size_t)(b*NCH+c)*D_ + t];
  float val = avg*avg; if(t==0) val = -val;      // linner(avg,avg) contribution
  red[t]=val; __syncthreads();
  for(int st=128;st>0;st>>=1){ if(t<st) red[t]+=red[t+st]; __syncthreads(); }
  float li = red[0];
  float denom = sqrtf(fmaxf(fabsf(li), 1e-8f));
  g_cb[b*D_+t] = avg/denom;
}

// centroid over batch of the per-batch centroids
__global__ void __launch_bounds__(256) kB(){
  __shared__ float red[256];
  int t = threadIdx.x;
  float avg=0.f;
#pragma unroll 4
  for(int b=0;b<B_;b++) avg += g_cb[b*D_+t];
  float val = avg*avg; if(t==0) val=-val;
  red[t]=val; __syncthreads();
  for(int st=128;st>0;st>>=1){ if(t<st) red[t]+=red[t+st]; __syncthreads(); }
  float li = red[0];
  float denom = sqrtf(fmaxf(fabsf(li),1e-8f));
  g_mean[t]=avg/denom;
}

// ---------------- Pass 2: per-feature sum/sumsq of x_t ----------------
// warp-per-row; lane owns features {4L..4L+3} and {128+4L..128+4L+3}
__global__ void __launch_bounds__(256) kC(const float4* __restrict__ x){
  int lane = threadIdx.x & 31, w = threadIdx.x >> 5;
  const float4* mv = (const float4*)g_mean;
  float4 mlo = mv[lane], mhi = mv[32+lane];
  float mean0 = __shfl_sync(0xffffffffu, mlo.x, 0);
  float m[8]  = {mlo.x,mlo.y,mlo.z,mlo.w,mhi.x,mhi.y,mhi.z,mhi.w};
  float ao[8] = {mlo.x,mlo.y,mlo.z,mlo.w,mhi.x,mhi.y,mhi.z,mhi.w};
  if(lane==0) ao[0] += 1.f;                      // add_origin(mean)
  float s[8] = {0,0,0,0,0,0,0,0};
  float q[8] = {0,0,0,0,0,0,0,0};

  auto accum = [&](float4 xlo, float4 xhi){
    float xr[8] = {xlo.x,xlo.y,xlo.z,xlo.w,xhi.x,xhi.y,xhi.z,xhi.w};
    float p = 0.f;
#pragma unroll
    for(int j=0;j<8;j++) p += m[j]*xr[j];
    if(lane==0) p -= 2.f*m[0]*xr[0];             // -> linner(mean, x)
    float li = wsum(p);
    float a = fmaxf(-li, 1.0f + CLAMPF);
    float f = acoshf(a) / sqrtf(a*a - 1.0f);
    float v[8];
#pragma unroll
    for(int j=0;j<8;j++) v[j] = f*(xr[j] - a*m[j]);
    float vz = __shfl_sync(0xffffffffu, v[0], 0);
    float coef = vz / (1.0f + mean0);
#pragma unroll
    for(int j=0;j<8;j++){ float t = v[j] - coef*ao[j]; s[j]+=t; q[j]+=t*t; }
  };

  int gw = blockIdx.x*8 + w, nw = gridDim.x*8;
  for(int r=gw; r<NROWS; r+=2*nw){
    int r2 = r + nw; bool h2 = r2 < NROWS;
    const float4* xr = x + (size_t)r*64;
    float4 xlo = xr[lane], xhi = xr[32+lane];
    float4 ylo, yhi;
    if(h2){ const float4* yr = x + (size_t)r2*64; ylo = yr[lane]; yhi = yr[32+lane]; }
    accum(xlo, xhi);
    if(h2) accum(ylo, yhi);
  }

  __shared__ float sh[8*512];
#pragma unroll
  for(int j=0;j<8;j++){
    int d = (j<4) ? (4*lane+j) : (128 + 4*lane + (j-4));
    sh[w*512 + d]       = s[j];
    sh[w*512 + 256 + d] = q[j];
  }
  __syncthreads();
  for(int i=threadIdx.x; i<512; i+=256){
    float acc=0.f;
#pragma unroll
    for(int ww=0; ww<8; ww++) acc += sh[ww*512 + i];
    g_part2[(size_t)blockIdx.x*512 + i] = acc;
  }
}

// deterministic finalize: var in double, g = gamma / sqrt(var + 1e-5)
__global__ void __launch_bounds__(256) kD(const float* __restrict__ gamma){
  int t = threadIdx.x;
  double ss=0.0, sq=0.0;
  for(int b=0;b<NBLK;b++){
    ss += (double)g_part2[(size_t)b*512 + t];
    sq += (double)g_part2[(size_t)b*512 + 256 + t];
  }
  double N = (double)NROWS;
  double mu = ss / N;
  double var = sq / N - mu*mu;
  g_scale[t] = (float)((double)gamma[0] / sqrt(var + 1e-5));
}

// ---------------- Pass 3: recompute x_t, scale, transp0(beta), expmap ----------------
__global__ void __launch_bounds__(256) kE(const float4* __restrict__ x,
                                          float4* __restrict__ out,
                                          const float* __restrict__ beta){
  int lane = threadIdx.x & 31, w = threadIdx.x >> 5;
  const float4* mv = (const float4*)g_mean;
  float4 mlo = mv[lane], mhi = mv[32+lane];
  float mean0 = __shfl_sync(0xffffffffu, mlo.x, 0);
  float m[8]  = {mlo.x,mlo.y,mlo.z,mlo.w,mhi.x,mhi.y,mhi.z,mhi.w};
  float ao[8] = {mlo.x,mlo.y,mlo.z,mlo.w,mhi.x,mhi.y,mhi.z,mhi.w};
  if(lane==0) ao[0] += 1.f;
  const float4* gv = (const float4*)g_scale;
  float4 glo = gv[lane], ghi = gv[32+lane];
  float g[8] = {glo.x,glo.y,glo.z,glo.w,ghi.x,ghi.y,ghi.z,ghi.w};
  const float4* bv = (const float4*)beta;
  float4 blo = bv[lane], bhi = bv[32+lane];
  float beta0 = __shfl_sync(0xffffffffu, blo.x, 0);
  float bb[8] = {blo.x,blo.y,blo.z,blo.w,bhi.x,bhi.y,bhi.z,bhi.w};
  float bo[8] = {blo.x,blo.y,blo.z,blo.w,bhi.x,bhi.y,bhi.z,bhi.w};
  if(lane==0) bo[0] += 1.f;                       // add_origin(beta)

  auto emit = [&](float4 xlo, float4 xhi, float4* dst){
    float xr[8] = {xlo.x,xlo.y,xlo.z,xlo.w,xhi.x,xhi.y,xhi.z,xhi.w};
    float p = 0.f;
#pragma unroll
    for(int j=0;j<8;j++) p += m[j]*xr[j];
    if(lane==0) p -= 2.f*m[0]*xr[0];
    float li = wsum(p);                           // linner(mean, x)
    float a = fmaxf(-li, 1.0f + CLAMPF);
    float f = acoshf(a) / sqrtf(a*a - 1.0f);
    float v[8];
#pragma unroll
    for(int j=0;j<8;j++) v[j] = f*(xr[j] - a*m[j]);
    float vz = __shfl_sync(0xffffffffu, v[0], 0);
    float coef = vz / (1.0f + mean0);
    float wv[8];
#pragma unroll
    for(int j=0;j<8;j++) wv[j] = (v[j] - coef*ao[j]) * g[j];
    // transp0(beta, wv): coef2 = linner(beta, wv)/(1+beta0)
    float p2 = 0.f;
#pragma unroll
    for(int j=0;j<8;j++) p2 += bb[j]*wv[j];
    if(lane==0) p2 -= 2.f*bb[0]*wv[0];
    float li2 = wsum(p2);
    float coef2 = li2 / (1.0f + beta0);
    float tv[8];
#pragma unroll
    for(int j=0;j<8;j++) tv[j] = wv[j] + coef2*bo[j];
    // expmap(beta, tv)
    float p3 = 0.f;
#pragma unroll
    for(int j=0;j<8;j++) p3 += tv[j]*tv[j];
    if(lane==0) p3 -= 2.f*tv[0]*tv[0];
    float nn = wsum(p3);
    nn = fmaxf(nn, CLAMPF);
    float n = sqrtf(nn);
    float ch = coshf(n);
    float shn = sinhf(n) / n;
    float4 o1, o2;
    o1.x = ch*bb[0] + shn*tv[0];  o1.y = ch*bb[1] + shn*tv[1];
    o1.z = ch*bb[2] + shn*tv[2];  o1.w = ch*bb[3] + shn*tv[3];
    o2.x = ch*bb[4] + shn*tv[4];  o2.y = ch*bb[5] + shn*tv[5];
    o2.z = ch*bb[6] + shn*tv[6];  o2.w = ch*bb[7] + shn*tv[7];
    dst[lane] = o1; dst[32+lane] = o2;
  };

  int gw = blockIdx.x*8 + w, nw = gridDim.x*8;
  for(int r=gw; r<NROWS; r+=2*nw){
    int r2 = r + nw; bool h2 = r2 < NROWS;
    const float4* xr = x + (size_t)r*64;
    float4 xlo = xr[lane], xhi = xr[32+lane];
    float4 ylo, yhi;
    if(h2){ const float4* yr = x + (size_t)r2*64; ylo = yr[lane]; yhi = yr[32+lane]; }
    emit(xlo, xhi, out + (size_t)r*64);
    if(h2) emit(ylo, yhi, out + (size_t)r2*64);
  }
}

extern "C" void kernel_launch(void* const* d_in, const int* in_sizes, int n_in,
                              void* d_out, int out_size){
  const float* x = nullptr;
  const float* beta = nullptr;
  const float* gamma = nullptr;
  for(int i=0;i<n_in;i++){
    if(in_sizes[i] == B_*S_*D_)      x     = (const float*)d_in[i];
    else if(in_sizes[i] == D_)       beta  = (const float*)d_in[i];
    else if(in_sizes[i] == 1)        gamma = (const float*)d_in[i];
  }
  kA <<<B_*NCH, 256>>>(x);
  kA2<<<B_,     256>>>();
  kB <<<1,      256>>>();
  kC <<<NBLK,   256>>>((const float4*)x);
  kD <<<1,      256>>>(gamma);
  kE <<<NBLK,   256>>>((const float4*)x, (float4*)d_out, beta);
}

// round 2
// speedup vs baseline: 1.0553x; 1.0553x over previous
#include <cuda_runtime.h>
#include <math.h>

#define D_ 256
#define B_ 128
#define S_ 1024
#define NROWS (B_*S_)
#define NCH 8
#define NBLK 592
#define CLAMPF 1e-7f
#define FULLM 0xffffffffu

// ---- scratch (static device globals; no allocations) ----
__device__ float g_part1[B_*NCH*D_];   // per (batch, seq-chunk) feature sums
__device__ float g_cb[B_*D_];          // per-batch seq centroids (normalized)
__device__ float g_mean[D_];           // final Frechet-style centroid
__device__ float g_part2[NBLK*2*D_];   // per-block [sum(256) | sumsq(256)] partials
__device__ float g_scale[D_];          // gamma / sqrt(var + eps)

// ---------------- Pass 1: seq-chunk partial sums (float4) ----------------
__global__ void __launch_bounds__(256) kA(const float4* __restrict__ x){
  int t = threadIdx.x;
  int f4 = t & 63, rg = t >> 6;
  int b = blockIdx.x / NCH, c = blockIdx.x % NCH;
  const float4* p = x + ((size_t)b*S_ + (size_t)c*(S_/NCH))*64 + f4;
  float4 acc = {0.f,0.f,0.f,0.f};
#pragma unroll 8
  for(int s=rg; s<S_/NCH; s+=4){
    float4 v = p[(size_t)s*64];
    acc.x += v.x; acc.y += v.y; acc.z += v.z; acc.w += v.w;
  }
  __shared__ float4 sh[256];
  sh[t] = acc; __syncthreads();
  if(t < 64){
    float4 a0 = sh[t], a1 = sh[64+t], a2 = sh[128+t], a3 = sh[192+t];
    float4 r;
    r.x = a0.x+a1.x+a2.x+a3.x; r.y = a0.y+a1.y+a2.y+a3.y;
    r.z = a0.z+a1.z+a2.z+a3.z; r.w = a0.w+a1.w+a2.w+a3.w;
    ((float4*)g_part1)[(size_t)blockIdx.x*64 + t] = r;
  }
}

// centroid over seq per batch (normalization is scale invariant: skip /S)
__global__ void __launch_bounds__(256) kA2(){
  __shared__ float red[256];
  int b = blockIdx.x, t = threadIdx.x;
  float avg = 0.f;
#pragma unroll
  for(int c=0;c<NCH;c++) avg += g_part1[(size_t)(b*NCH+c)*D_ + t];
  float val = avg*avg; if(t==0) val = -val;
  red[t]=val; __syncthreads();
  for(int st=128;st>0;st>>=1){ if(t<st) red[t]+=red[t+st]; __syncthreads(); }
  float denom = sqrtf(fmaxf(fabsf(red[0]), 1e-8f));
  g_cb[b*D_+t] = avg/denom;
}

// centroid over batch of the per-batch centroids
__global__ void __launch_bounds__(256) kB(){
  __shared__ float red[256];
  int t = threadIdx.x;
  float avg=0.f;
#pragma unroll 4
  for(int b=0;b<B_;b++) avg += g_cb[b*D_+t];
  float val = avg*avg; if(t==0) val=-val;
  red[t]=val; __syncthreads();
  for(int st=128;st>0;st>>=1){ if(t<st) red[t]+=red[t+st]; __syncthreads(); }
  float denom = sqrtf(fmaxf(fabsf(red[0]),1e-8f));
  g_mean[t]=avg/denom;
}

// ---------------- Pass 2: per-feature sum/sumsq of x_t ----------------
__global__ void __launch_bounds__(256) kC(const float4* __restrict__ x){
  int lane = threadIdx.x & 31, w = threadIdx.x >> 5;
  const float4* mv = (const float4*)g_mean;
  float4 mlo = mv[lane], mhi = mv[32+lane];
  float mean0 = __shfl_sync(FULLM, mlo.x, 0);
  float inv1m = 1.f/(1.f + mean0);
  float m[8]  = {mlo.x,mlo.y,mlo.z,mlo.w,mhi.x,mhi.y,mhi.z,mhi.w};
  float s[8] = {0,0,0,0,0,0,0,0};
  float q[8] = {0,0,0,0,0,0,0,0};

  auto accum = [&](float4 xlo, float4 xhi){
    float xr[8] = {xlo.x,xlo.y,xlo.z,xlo.w,xhi.x,xhi.y,xhi.z,xhi.w};
    float x0 = __shfl_sync(FULLM, xr[0], 0);    // overlaps with butterfly below
    float p = 0.f;
#pragma unroll
    for(int j=0;j<8;j++) p += m[j]*xr[j];
    if(lane==0) p -= 2.f*m[0]*xr[0];            // -> linner(mean, x)
#pragma unroll
    for(int o=16;o>0;o>>=1) p += __shfl_xor_sync(FULLM, p, o);
    float a = fmaxf(-p, 1.0f + CLAMPF);
    float f = acoshf(a) * rsqrtf(a*a - 1.0f);
    float coef = f*(x0 - a*mean0) * inv1m;      // lane0's v0 / (1+mean0), all lanes
    float t8[8];
#pragma unroll
    for(int j=0;j<8;j++) t8[j] = f*(xr[j] - a*m[j]) - coef*m[j];
    if(lane==0) t8[0] -= coef;                  // ao[0] = mean0 + 1
#pragma unroll
    for(int j=0;j<8;j++){ s[j]+=t8[j]; q[j] = fmaf(t8[j], t8[j], q[j]); }
  };

  int gw = blockIdx.x*8 + w, nw = gridDim.x*8;
  for(int r=gw; r<NROWS; r+=2*nw){
    int r2 = r + nw; bool h2 = r2 < NROWS;
    const float4* xr = x + (size_t)r*64;
    float4 xlo = xr[lane], xhi = xr[32+lane];
    float4 ylo, yhi;
    if(h2){ const float4* yr = x + (size_t)r2*64; ylo = yr[lane]; yhi = yr[32+lane]; }
    accum(xlo, xhi);
    if(h2) accum(ylo, yhi);
  }

  __shared__ float sh[8*512];
#pragma unroll
  for(int j=0;j<8;j++){
    int d = (j<4) ? (4*lane+j) : (128 + 4*lane + (j-4));
    sh[w*512 + d]       = s[j];
    sh[w*512 + 256 + d] = q[j];
  }
  __syncthreads();
  for(int i=threadIdx.x; i<512; i+=256){
    float acc=0.f;
#pragma unroll
    for(int ww=0; ww<8; ww++) acc += sh[ww*512 + i];
    g_part2[(size_t)blockIdx.x*512 + i] = acc;
  }
}

// deterministic finalize: var in double, g = gamma / sqrt(var + 1e-5)
__global__ void __launch_bounds__(256) kD(const float* __restrict__ gamma){
  int t = threadIdx.x;
  double ss=0.0, sq=0.0;
  for(int b=0;b<NBLK;b++){
    ss += (double)g_part2[(size_t)b*512 + t];
    sq += (double)g_part2[(size_t)b*512 + 256 + t];
  }
  double N = (double)NROWS;
  double mu = ss / N;
  double var = sq / N - mu*mu;
  g_scale[t] = (float)((double)gamma[0] / sqrt(var + 1e-5));
}

// ---------------- Pass 3: recompute x_t, scale, transp0(beta), expmap ----------------
__global__ void __launch_bounds__(256) kE(const float4* __restrict__ x,
                                          float4* __restrict__ out,
                                          const float* __restrict__ beta){
  int lane = threadIdx.x & 31, w = threadIdx.x >> 5;
  const float4* mv = (const float4*)g_mean;
  float4 mlo = mv[lane], mhi = mv[32+lane];
  float mean0 = __shfl_sync(FULLM, mlo.x, 0);
  float inv1m = 1.f/(1.f + mean0);
  float m[8]  = {mlo.x,mlo.y,mlo.z,mlo.w,mhi.x,mhi.y,mhi.z,mhi.w};
  const float4* gv = (const float4*)g_scale;
  float4 glo = gv[lane], ghi = gv[32+lane];
  float g[8] = {glo.x,glo.y,glo.z,glo.w,ghi.x,ghi.y,ghi.z,ghi.w};
  float g0 = __shfl_sync(FULLM, glo.x, 0);
  const float4* bv = (const float4*)beta;
  float4 blo = bv[lane], bhi = bv[32+lane];
  float beta0 = __shfl_sync(FULLM, blo.x, 0);
  float inv1b = 1.f/(1.f + beta0);
  float lbo = -2.f - 2.f*beta0;                 // linner(beta+o, beta+o)
  float bb[8] = {blo.x,blo.y,blo.z,blo.w,bhi.x,bhi.y,bhi.z,bhi.w};

  auto emit = [&](float4 xlo, float4 xhi, float4* dst){
    float xr[8] = {xlo.x,xlo.y,xlo.z,xlo.w,xhi.x,xhi.y,xhi.z,xhi.w};
    float x0 = __shfl_sync(FULLM, xr[0], 0);
    float p = 0.f;
#pragma unroll
    for(int j=0;j<8;j++) p += m[j]*xr[j];
    if(lane==0) p -= 2.f*m[0]*xr[0];
#pragma unroll
    for(int o=16;o>0;o>>=1) p += __shfl_xor_sync(FULLM, p, o);
    float a = fmaxf(-p, 1.0f + CLAMPF);
    float f = acoshf(a) * rsqrtf(a*a - 1.0f);
    float v0   = f*(x0 - a*mean0);              // lane0's v[0], all lanes
    float coef = v0 * inv1m;
    float wv[8];
#pragma unroll
    for(int j=0;j<8;j++) wv[j] = (f*(xr[j] - a*m[j]) - coef*m[j]) * g[j];
    if(lane==0) wv[0] -= coef*g[0];
    float wv0 = (v0 - coef*(mean0 + 1.f)) * g0; // lane0's wv[0], all lanes (≈0)
    // combined reductions: pB = linner(beta, wv), pC = linner(wv, wv)
    float pB = 0.f, pC = 0.f;
#pragma unroll
    for(int j=0;j<8;j++){ pB += bb[j]*wv[j]; pC = fmaf(wv[j], wv[j], pC); }
    if(lane==0){ pB -= 2.f*bb[0]*wv[0]; pC -= 2.f*wv[0]*wv[0]; }
#pragma unroll
    for(int o=16;o>0;o>>=1){
      pB += __shfl_xor_sync(FULLM, pB, o);
      pC += __shfl_xor_sync(FULLM, pC, o);
    }
    float coef2 = pB * inv1b;
    // linner(tv,tv) = pC + 2*coef2*linner(wv, beta+o) + coef2^2*linner(beta+o,beta+o)
    float nn = pC + 2.f*coef2*(pB - wv0) + coef2*coef2*lbo;
    nn = fmaxf(nn, CLAMPF);
    float n = sqrtf(nn);
    float ch = coshf(n);
    float shn = sinhf(n) / n;
    float o8[8];
#pragma unroll
    for(int j=0;j<8;j++) o8[j] = ch*bb[j] + shn*(wv[j] + coef2*bb[j]);
    if(lane==0) o8[0] += shn*coef2;             // bo[0] = bb[0] + 1
    float4 o1 = {o8[0],o8[1],o8[2],o8[3]};
    float4 o2 = {o8[4],o8[5],o8[6],o8[7]};
    dst[lane] = o1; dst[32+lane] = o2;
  };

  int gw = blockIdx.x*8 + w, nw = gridDim.x*8;
  for(int r=gw; r<NROWS; r+=2*nw){
    int r2 = r + nw; bool h2 = r2 < NROWS;
    const float4* xr = x + (size_t)r*64;
    float4 xlo = xr[lane], xhi = xr[32+lane];
    float4 ylo, yhi;
    if(h2){ const float4* yr = x + (size_t)r2*64; ylo = yr[lane]; yhi = yr[32+lane]; }
    emit(xlo, xhi, out + (size_t)r*64);
    if(h2) emit(ylo, yhi, out + (size_t)r2*64);
  }
}

extern "C" void kernel_launch(void* const* d_in, const int* in_sizes, int n_in,
                              void* d_out, int out_size){
  const float* x = nullptr;
  const float* beta = nullptr;
  const float* gamma = nullptr;
  for(int i=0;i<n_in;i++){
    if(in_sizes[i] == B_*S_*D_)      x     = (const float*)d_in[i];
    else if(in_sizes[i] == D_)       beta  = (const float*)d_in[i];
    else if(in_sizes[i] == 1)        gamma = (const float*)d_in[i];
  }
  kA <<<B_*NCH, 256>>>((const float4*)x);
  kA2<<<B_,     256>>>();
  kB <<<1,      256>>>();
  kC <<<NBLK,   256>>>((const float4*)x);
  kD <<<1,      256>>>(gamma);
  kE <<<NBLK,   256>>>((const float4*)x, (float4*)d_out, beta);
}